// round 11
// baseline (speedup 1.0000x reference)
#include <cuda_runtime.h>
#include <cuda_fp16.h>
#include <cstdint>

#define B_   64
#define NR_  16384
#define IC_  16
#define NC_  10
#define OC_  16
#define CO_  160
#define SPLITK 16
#define KCH  (NR_/SPLITK)   // 1024
#define KB   32
#define NCH  (KCH/KB)       // 32
#define CSCALE (1.0f/524288.0f)   // 2^-19

// -------- device scratch (no allocations allowed) --------
__device__ __half   g_xh [(size_t)IC_*B_*NR_];          // x fp16 hi [i][b][r]
__device__ uint32_t g_ah8[(size_t)IC_*B_*NR_/4];        // s8 rni(x*16), packed x4
__device__ uint32_t g_al8[(size_t)IC_*B_*NR_/4];        // s8 rni((x-hi)*2^15)
__device__ float g_part[(size_t)SPLITK*B_*IC_*CO_];     // split-K partials
__device__ float g_fcp[NC_*B_];                         // fc partial dots [c][b]
__device__ int   g_ctr = 0;

// smem byte offsets (k_gemm):
//  W fp16 hi : 2 x 160x80B   -> 0      (25600)
//  W s8 hi   : 2 x 160x48B   -> 25600  (15360)
//  W s8 lo   : 2 x 160x48B   -> 40960  (15360)
//  x fp16 hi : 4 x 64x80B    -> 56320  (20480)
//  x s8 hi   : 4 x 64x48B    -> 76800  (12288)
//  x s8 lo   : 4 x 64x48B    -> 89088  (12288)
#define WH_O  0
#define W8H_O 25600
#define W8L_O 40960
#define XH_O  56320
#define X8H_O 76800
#define X8L_O 89088
#define SMEM_G 101376

static __device__ __forceinline__ void mma16816(float* c, const uint32_t* a,
                                                const uint32_t* b) {
    asm volatile(
        "mma.sync.aligned.m16n8k16.row.col.f32.f16.f16.f32 "
        "{%0,%1,%2,%3}, {%4,%5,%6,%7}, {%8,%9}, {%0,%1,%2,%3};"
        : "+f"(c[0]), "+f"(c[1]), "+f"(c[2]), "+f"(c[3])
        : "r"(a[0]), "r"(a[1]), "r"(a[2]), "r"(a[3]), "r"(b[0]), "r"(b[1]));
}
static __device__ __forceinline__ void imma16832(int* c, const uint32_t* a,
                                                 const uint32_t* b) {
    asm volatile(
        "mma.sync.aligned.m16n8k32.row.col.s32.s8.s8.s32 "
        "{%0,%1,%2,%3}, {%4,%5,%6,%7}, {%8,%9}, {%0,%1,%2,%3};"
        : "+r"(c[0]), "+r"(c[1]), "+r"(c[2]), "+r"(c[3])
        : "r"(a[0]), "r"(a[1]), "r"(a[2]), "r"(a[3]), "r"(b[0]), "r"(b[1]));
}
static __device__ __forceinline__ void ldsm4(uint32_t* r, uint32_t addr) {
    asm volatile("ldmatrix.sync.aligned.m8n8.x4.shared.b16 {%0,%1,%2,%3}, [%4];"
                 : "=r"(r[0]), "=r"(r[1]), "=r"(r[2]), "=r"(r[3]) : "r"(addr));
}
static __device__ __forceinline__ void ldsm2(uint32_t* r, uint32_t addr) {
    asm volatile("ldmatrix.sync.aligned.m8n8.x2.shared.b16 {%0,%1}, [%2];"
                 : "=r"(r[0]), "=r"(r[1]) : "r"(addr));
}
static __device__ __forceinline__ uint32_t smem_u32(const void* p) {
    uint32_t a;
    asm("{ .reg .u64 t; cvta.to.shared.u64 t, %1; cvt.u32.u64 %0, t; }"
        : "=r"(a) : "l"(p));
    return a;
}
static __device__ __forceinline__ void cp16(uint32_t dst, const void* src) {
    asm volatile("cp.async.cg.shared.global [%0], [%1], 16;" :: "r"(dst), "l"(src));
}
static __device__ __forceinline__ void cp8(uint32_t dst, const void* src) {
    asm volatile("cp.async.ca.shared.global [%0], [%1], 8;" :: "r"(dst), "l"(src));
}
static __device__ __forceinline__ void cp_commit() {
    asm volatile("cp.async.commit_group;" ::: "memory");
}
template <int N> static __device__ __forceinline__ void cp_wait() {
    asm volatile("cp.async.wait_group %0;" :: "n"(N) : "memory");
}
// pack 4 ints -> s8x4 (saturating), byte0 = i0
static __device__ __forceinline__ uint32_t pack_s8(int i0, int i1, int i2, int i3) {
    uint32_t t, d;
    asm("cvt.pack.sat.s8.s32.b32 %0, %1, %2, 0;" : "=r"(t) : "r"(i3), "r"(i2));
    asm("cvt.pack.sat.s8.s32.b32 %0, %1, %2, %3;" : "=r"(d) : "r"(i1), "r"(i0), "r"(t));
    return d;
}

// ---------------------------------------------------------------------------
// 1) Transpose x[b][r][i] -> fp16 hi + s8(x*16) + s8(residual*2^15), [i][b][r]
// ---------------------------------------------------------------------------
__global__ void k_transpose(const float* __restrict__ x) {
    __shared__ float tile[16][64];
    const int b = blockIdx.y, tid = threadIdx.x;
    const int r = tid >> 2, i4 = (tid & 3) * 4;
    const int i = tid >> 4, rs = (tid & 15) * 4;
    for (int tt = 0; tt < 4; tt++) {
        const int r0 = (blockIdx.x * 4 + tt) * 64;
        float4 v = *(const float4*)(x + ((size_t)b * NR_ + r0 + r) * IC_ + i4);
        tile[i4 + 0][r] = v.x; tile[i4 + 1][r] = v.y;
        tile[i4 + 2][r] = v.z; tile[i4 + 3][r] = v.w;
        __syncthreads();
        float4 o = *(const float4*)&tile[i][rs];
        union { __half2 h[2]; uint2 u; } ph;
        ph.h[0] = __floats2half2_rn(o.x, o.y);
        ph.h[1] = __floats2half2_rn(o.z, o.w);
        float hx = __half2float(__low2half(ph.h[0]));
        float hy = __half2float(__high2half(ph.h[0]));
        float hz = __half2float(__low2half(ph.h[1]));
        float hw = __half2float(__high2half(ph.h[1]));
        uint32_t a8 = pack_s8(__float2int_rn(o.x * 16.f), __float2int_rn(o.y * 16.f),
                              __float2int_rn(o.z * 16.f), __float2int_rn(o.w * 16.f));
        uint32_t l8 = pack_s8(__float2int_rn((o.x - hx) * 32768.f),
                              __float2int_rn((o.y - hy) * 32768.f),
                              __float2int_rn((o.z - hz) * 32768.f),
                              __float2int_rn((o.w - hw) * 32768.f));
        const size_t dst = ((size_t)i * B_ + b) * NR_ + r0 + rs;
        *(uint2*)(g_xh + dst) = ph.u;
        g_ah8[dst >> 2] = a8;
        g_al8[dst >> 2] = l8;
        __syncthreads();
    }
}

// ---------------------------------------------------------------------------
// 2) fp16-main + s8-correction GEMM. grid (SPLITK, IC), 256 threads.
//    Per k32: 2 HMMA (ah*wh) + 2 IMMA (al*W8 + x8*wl), scale 2^-19.
// ---------------------------------------------------------------------------
__global__ __launch_bounds__(256, 2) void k_gemm(const float* __restrict__ Wg) {
    extern __shared__ char smem[];
    const uint32_t sb = smem_u32(smem);

    const int i = blockIdx.y, split = blockIdx.x, t = threadIdx.x;
    const int warp = t >> 5, lane = t & 31;
    const int wm = warp >> 2, wn = warp & 3;
    const int r0 = split * KCH;
    const float* Wi = Wg + (size_t)i * CO_ * NR_;
    const __half* Xh = g_xh + (size_t)i * B_ * NR_;
    const char* Ah8 = (const char*)g_ah8 + (size_t)i * B_ * NR_;
    const char* Al8 = (const char*)g_al8 + (size_t)i * B_ * NR_;

    float acc[2][5][4];
#pragma unroll
    for (int m = 0; m < 2; m++)
#pragma unroll
        for (int n = 0; n < 5; n++)
#pragma unroll
            for (int q = 0; q < 4; q++) acc[m][n][q] = 0.f;

    // ldmatrix lane-address components (byte units)
    const int tA = lane >> 3;
    const int a_ml = (tA & 1) * 8 + (lane & 7);    // m row within 16
    const int a_kb = (tA >> 1) * 16;               // k byte offset 0/16
    const int b_bn = lane & 7;
    const int b_kb = (tA & 1) * 16;
    const int b_p  = tA >> 1;
    const int tC   = (lane >> 3) & 1;

    const int wrow = t >> 3, wk4 = t & 7;          // W LDG: 5 rows strided 32
    float4 wr[5];

#define LDGW(nn) { \
        const float* wp = Wi + (size_t)wrow * NR_ + r0 + (nn) * KB + wk4 * 4; \
        _Pragma("unroll") \
        for (int q = 0; q < 5; q++) wr[q] = *(const float4*)(wp + (size_t)q * 32 * NR_); }

#define XCP(nn, ss) { \
        const int xrow = t >> 2, x4 = t & 3; \
        const size_t eo = (size_t)xrow * NR_ + r0 + (nn) * KB; \
        cp16(sb + XH_O  + (ss) * 5120 + xrow * 80 + x4 * 16, Xh + eo + x4 * 8); \
        cp8 (sb + X8H_O + (ss) * 3072 + xrow * 48 + x4 * 8,  Ah8 + eo + x4 * 8); \
        cp8 (sb + X8L_O + (ss) * 3072 + xrow * 48 + x4 * 8,  Al8 + eo + x4 * 8); \
        cp_commit(); }

    XCP(0, 0);
    XCP(1, 1);
    LDGW(0);

    for (int n = 0; n < NCH; n++) {
        const int s2 = n & 1, s4 = n & 3;
        if (n + 2 < NCH) XCP(n + 2, (n + 2) & 3);
        // convert W chunk n (regs from prev iter) -> stage s2
#pragma unroll
        for (int q = 0; q < 5; q++) {
            const float4 w = wr[q];
            union { __half2 h[2]; uint2 u; } ph;
            ph.h[0] = __floats2half2_rn(w.x, w.y);
            ph.h[1] = __floats2half2_rn(w.z, w.w);
            float hx = __half2float(__low2half(ph.h[0]));
            float hy = __half2float(__high2half(ph.h[0]));
            float hz = __half2float(__low2half(ph.h[1]));
            float hw = __half2float(__high2half(ph.h[1]));
            uint32_t h8 = pack_s8(__float2int_rn(w.x * 16.f), __float2int_rn(w.y * 16.f),
                                  __float2int_rn(w.z * 16.f), __float2int_rn(w.w * 16.f));
            uint32_t l8 = pack_s8(__float2int_rn((w.x - hx) * 32768.f),
                                  __float2int_rn((w.y - hy) * 32768.f),
                                  __float2int_rn((w.z - hz) * 32768.f),
                                  __float2int_rn((w.w - hw) * 32768.f));
            const int row = wrow + q * 32;
            *(uint2*)(smem + WH_O + s2 * 12800 + row * 80 + wk4 * 8) = ph.u;
            *(uint32_t*)(smem + W8H_O + s2 * 7680 + row * 48 + wk4 * 4) = h8;
            *(uint32_t*)(smem + W8L_O + s2 * 7680 + row * 48 + wk4 * 4) = l8;
        }
        if (n + 2 < NCH)      cp_wait<2>();
        else if (n + 1 < NCH) cp_wait<1>();
        else                  cp_wait<0>();
        __syncthreads();
        if (n + 1 < NCH) LDGW(n + 1);

        const uint32_t whp = sb + WH_O  + s2 * 12800;
        const uint32_t w8h = sb + W8H_O + s2 * 7680;
        const uint32_t w8l = sb + W8L_O + s2 * 7680;
        const uint32_t xhp = sb + XH_O  + s4 * 5120;
        const uint32_t x8h = sb + X8H_O + s4 * 3072;
        const uint32_t x8l = sb + X8L_O + s4 * 3072;

        // ---- s8 corrections (one k32 covers the whole chunk) ----
        {
            uint32_t a8h[2][4], a8l[2][4];
#pragma unroll
            for (int mt = 0; mt < 2; mt++) {
                const uint32_t ro = (uint32_t)((wm * 32 + mt * 16 + a_ml) * 48 + a_kb);
                ldsm4(a8h[mt], x8h + ro);
                ldsm4(a8l[mt], x8l + ro);
            }
            uint32_t b8h[5][2], b8l[5][2];
#pragma unroll
            for (int p = 0; p < 2; p++) {
                const uint32_t ro =
                    (uint32_t)((wn * 40 + (2 * p + b_p) * 8 + b_bn) * 48 + b_kb);
                ldsm4(&b8h[2 * p][0], w8h + ro);
                ldsm4(&b8l[2 * p][0], w8l + ro);
            }
            {
                const uint32_t ro = (uint32_t)((wn * 40 + 32 + b_bn) * 48 + tC * 16);
                ldsm2(&b8h[4][0], w8h + ro);
                ldsm2(&b8l[4][0], w8l + ro);
            }
#pragma unroll
            for (int mt = 0; mt < 2; mt++)
#pragma unroll
                for (int nf = 0; nf < 5; nf++) {
                    int d[4] = {0, 0, 0, 0};
                    imma16832(d, a8l[mt], b8h[nf]);   // al * W8
                    imma16832(d, a8h[mt], b8l[nf]);   // x8 * wl
#pragma unroll
                    for (int q = 0; q < 4; q++)
                        acc[mt][nf][q] += (float)d[q] * CSCALE;
                }
        }

        // ---- fp16 main term (2 x k16) ----
#pragma unroll
        for (int kb = 0; kb < 2; kb++) {
            uint32_t a[2][4];
#pragma unroll
            for (int mt = 0; mt < 2; mt++)
                ldsm4(a[mt], xhp + (uint32_t)((wm * 32 + mt * 16 + a_ml) * 80
                                              + kb * 32 + a_kb));
            uint32_t bh[5][2];
#pragma unroll
            for (int p = 0; p < 2; p++)
                ldsm4(&bh[2 * p][0],
                      whp + (uint32_t)((wn * 40 + (2 * p + b_p) * 8 + b_bn) * 80
                                       + kb * 32 + b_kb));
            ldsm2(&bh[4][0],
                  whp + (uint32_t)((wn * 40 + 32 + b_bn) * 80 + kb * 32 + tC * 16));
#pragma unroll
            for (int mt = 0; mt < 2; mt++)
#pragma unroll
                for (int nf = 0; nf < 5; nf++)
                    mma16816(acc[mt][nf], a[mt], bh[nf]);
        }
    }

    // epilogue: g_part[split][b][i][co]
    float* base = g_part + (size_t)split * (B_ * IC_ * CO_) + (size_t)i * CO_;
#pragma unroll
    for (int mt = 0; mt < 2; mt++) {
        const int b = wm * 32 + mt * 16 + (lane >> 2);
#pragma unroll
        for (int nf = 0; nf < 5; nf++) {
            const int co = wn * 40 + nf * 8 + (lane & 3) * 2;
            float* d0 = base + (size_t)b * (IC_ * CO_) + co;
            *(float2*)d0 = make_float2(acc[mt][nf][0], acc[mt][nf][1]);
            *(float2*)(d0 + 8 * IC_ * CO_) =
                make_float2(acc[mt][nf][2], acc[mt][nf][3]);   // b+8
        }
    }
}

// ---------------------------------------------------------------------------
// 3) Fused split-K reduce + routing + v + fc partials + (last CTA) final pred.
// ---------------------------------------------------------------------------
#define ISTR 1032
__global__ __launch_bounds__(1024) void k_route_all(const float* __restrict__ fcw,
                                                    const float* __restrict__ fcb,
                                                    float* __restrict__ out) {
    extern __shared__ float sm[];
    float* u_s  = sm;                       // [16][ISTR]
    float* v_s  = sm + 16 * ISTR;           // [1024]
    float* csh  = v_s + 1024;               // [16]
    float* bijs = csh + 16;                 // [16]
    float* ared = bijs + 16;                // [32]
    __shared__ int last;
    const int c = blockIdx.x, t = threadIdx.x;

    {   // split-K reduce from L2-resident g_part
        const int o4 = t & 3, i = (t >> 2) & 15, b0 = t >> 6;
#pragma unroll
        for (int j = 0; j < 4; j++) {
            const int b = b0 + 16 * j;
            const size_t off = ((size_t)b * IC_ + i) * CO_ + c * OC_ + o4 * 4;
            float4 s = make_float4(0.f, 0.f, 0.f, 0.f);
#pragma unroll
            for (int sp = 0; sp < SPLITK; sp++) {
                float4 p = *(const float4*)(g_part + (size_t)sp * (B_ * IC_ * CO_) + off);
                s.x += p.x; s.y += p.y; s.z += p.z; s.w += p.w;
            }
            *(float4*)(u_s + i * ISTR + b * 16 + o4 * 4) = s;
        }
    }
    if (t < 16) bijs[t] = 0.f;
    __syncthreads();

    for (int it = 0; it < 3; it++) {
        if (t < 32) {   // softmax over i, width-16 shuffles
            float bv = (t < 16) ? bijs[t] : -1e30f;
            float m = bv;
#pragma unroll
            for (int off = 8; off; off >>= 1)
                m = fmaxf(m, __shfl_xor_sync(0xffffffffu, m, off, 16));
            float e = expf(bv - m), sum = e;
#pragma unroll
            for (int off = 8; off; off >>= 1)
                sum += __shfl_xor_sync(0xffffffffu, sum, off, 16);
            if (t < 16) csh[t] = e / sum;
        }
        __syncthreads();
        {
            float s = 0.f;
#pragma unroll
            for (int i = 0; i < IC_; i++) s += csh[i] * u_s[i * ISTR + t];
            v_s[t] = s * fabsf(s) / (1.f + s * s);
        }
        __syncthreads();
        if (it < 2) {   // agreement
            const int w = t >> 5, l = t & 31;
            const int i = w & 15, j0 = (w >> 4) * 512;
            float a = 0.f;
            for (int j = j0 + l; j < j0 + 512; j += 32)
                a += u_s[i * ISTR + j] * v_s[j];
#pragma unroll
            for (int off = 16; off; off >>= 1)
                a += __shfl_down_sync(0xffffffffu, a, off);
            if (l == 0) ared[(w >> 4) * 16 + i] = a;
            __syncthreads();
            if (t < 16) bijs[t] += (ared[t] + ared[16 + t]) * (1.0f / B_);
            __syncthreads();
        }
    }
    {
        const int b = t >> 4, o = t & 15;
        const float v = v_s[t];
        out[B_ + b * CO_ + c * OC_ + o] = v;
        float p = v * fcw[c * OC_ + o];
#pragma unroll
        for (int off = 8; off; off >>= 1)
            p += __shfl_down_sync(0xffffffffu, p, off, 16);
        if (o == 0) g_fcp[c * B_ + b] = p;
    }
    // last CTA computes pred (deterministic sum over fixed c order)
    __threadfence();
    if (t == 0) last = (atomicAdd(&g_ctr, 1) == NC_ - 1);
    __syncthreads();
    if (last) {
        if (t < B_) {
            float s = fcb[0];
#pragma unroll
            for (int cc = 0; cc < NC_; cc++) s += g_fcp[cc * B_ + t];
            out[t] = 1.f / (1.f + expf(-s));
        }
        if (t == 0) g_ctr = 0;   // reset for next graph replay
    }
}

// ---------------------------------------------------------------------------
extern "C" void kernel_launch(void* const* d_in, const int* in_sizes, int n_in,
                              void* d_out, int out_size) {
    const float* x   = (const float*)d_in[0];
    const float* W   = (const float*)d_in[1];
    const float* fcw = (const float*)d_in[2];
    const float* fcb = (const float*)d_in[3];
    float* out = (float*)d_out;

    const int route_smem = (16 * ISTR + 1024 + 16 + 16 + 32) * 4;
    cudaFuncSetAttribute(k_gemm, cudaFuncAttributeMaxDynamicSharedMemorySize, SMEM_G);
    cudaFuncSetAttribute(k_route_all, cudaFuncAttributeMaxDynamicSharedMemorySize,
                         route_smem);

    k_transpose<<<dim3(NR_ / 256, B_), 256>>>(x);
    k_gemm<<<dim3(SPLITK, IC_), 256, SMEM_G>>>(W);
    k_route_all<<<NC_, 1024, route_smem>>>(fcw, fcb, out);
}

// round 12
// speedup vs baseline: 1.6866x; 1.6866x over previous
#include <cuda_runtime.h>
#include <cuda_fp16.h>
#include <cstdint>

#define B_   64
#define NR_  16384
#define IC_  16
#define NC_  10
#define OC_  16
#define CO_  160
#define KB   32
#define SMAX 19              // max splits per i (i<8: 19, i>=8: 18)

// -------- device scratch (no allocations allowed) --------
__device__ __half g_xhi[(size_t)IC_*B_*NR_];            // x hi fp16 [i][b][r]
__device__ __half g_xlo[(size_t)IC_*B_*NR_];            // x residual fp16
__device__ float g_part[(size_t)SMAX*B_*IC_*CO_];       // split-K partials [s][b][i][co]
__device__ float g_fcp[NC_*B_];                         // fc partial dots [c][b]
__device__ int   g_ctr = 0;

// GEMM smem byte offsets (rows padded to 40 halves = 80B)
#define WSH_OFF 0            // W hi: 2 stages x 160x40 halves
#define WSL_OFF 25600        // W lo
#define XSH_OFF 51200        // x hi: 3 stages x 64x40 halves
#define XSL_OFF 66560        // x lo
#define SMEM_G  81920

static __device__ __forceinline__ void mma16816(float* c, const uint32_t* a,
                                                const uint32_t* b) {
    asm volatile(
        "mma.sync.aligned.m16n8k16.row.col.f32.f16.f16.f32 "
        "{%0,%1,%2,%3}, {%4,%5,%6,%7}, {%8,%9}, {%0,%1,%2,%3};"
        : "+f"(c[0]), "+f"(c[1]), "+f"(c[2]), "+f"(c[3])
        : "r"(a[0]), "r"(a[1]), "r"(a[2]), "r"(a[3]), "r"(b[0]), "r"(b[1]));
}
// fp16-accumulator variant (corrections): D,C = 2 x .f16x2 regs
static __device__ __forceinline__ void mma16816h(uint32_t* c, const uint32_t* a,
                                                 const uint32_t* b) {
    asm volatile(
        "mma.sync.aligned.m16n8k16.row.col.f16.f16.f16.f16 "
        "{%0,%1}, {%2,%3,%4,%5}, {%6,%7}, {%0,%1};"
        : "+r"(c[0]), "+r"(c[1])
        : "r"(a[0]), "r"(a[1]), "r"(a[2]), "r"(a[3]), "r"(b[0]), "r"(b[1]));
}
static __device__ __forceinline__ void ldsm4(uint32_t* r, uint32_t addr) {
    asm volatile("ldmatrix.sync.aligned.m8n8.x4.shared.b16 {%0,%1,%2,%3}, [%4];"
                 : "=r"(r[0]), "=r"(r[1]), "=r"(r[2]), "=r"(r[3]) : "r"(addr));
}
static __device__ __forceinline__ void ldsm2(uint32_t* r, uint32_t addr) {
    asm volatile("ldmatrix.sync.aligned.m8n8.x2.shared.b16 {%0,%1}, [%2];"
                 : "=r"(r[0]), "=r"(r[1]) : "r"(addr));
}
static __device__ __forceinline__ uint32_t smem_u32(const void* p) {
    uint32_t a;
    asm("{ .reg .u64 t; cvta.to.shared.u64 t, %1; cvt.u32.u64 %0, t; }"
        : "=r"(a) : "l"(p));
    return a;
}
static __device__ __forceinline__ void cp16(uint32_t dst, const void* src) {
    asm volatile("cp.async.cg.shared.global [%0], [%1], 16;" :: "r"(dst), "l"(src));
}
static __device__ __forceinline__ void cp_commit() {
    asm volatile("cp.async.commit_group;" ::: "memory");
}
template <int N> static __device__ __forceinline__ void cp_wait() {
    asm volatile("cp.async.wait_group %0;" :: "n"(N) : "memory");
}
static __device__ __forceinline__ void hsplit(float v, __half& h, __half& l) {
    h = __float2half_rn(v);
    l = __float2half_rn(v - __half2float(h));
}

// ---------------------------------------------------------------------------
// 1) Transpose + fp16 hi/lo split: x[b][r][i] -> g_xhi/g_xlo [i][b][r]
// ---------------------------------------------------------------------------
__global__ void k_transpose(const float* __restrict__ x) {
    __shared__ float tile[16][64];
    const int b = blockIdx.y, tid = threadIdx.x;
    const int r = tid >> 2, i4 = (tid & 3) * 4;
    const int i = tid >> 4, rs = (tid & 15) * 4;
    for (int tt = 0; tt < 4; tt++) {
        const int r0 = (blockIdx.x * 4 + tt) * 64;
        float4 v = *(const float4*)(x + ((size_t)b * NR_ + r0 + r) * IC_ + i4);
        tile[i4 + 0][r] = v.x; tile[i4 + 1][r] = v.y;
        tile[i4 + 2][r] = v.z; tile[i4 + 3][r] = v.w;
        __syncthreads();
        float4 o = *(const float4*)&tile[i][rs];
        union { __half h[4]; uint2 u; } ph, pl;
        hsplit(o.x, ph.h[0], pl.h[0]);
        hsplit(o.y, ph.h[1], pl.h[1]);
        hsplit(o.z, ph.h[2], pl.h[2]);
        hsplit(o.w, ph.h[3], pl.h[3]);
        const size_t dst = ((size_t)i * B_ + b) * NR_ + r0 + rs;
        *(uint2*)(g_xhi + dst) = ph.u;
        *(uint2*)(g_xlo + dst) = pl.u;
        __syncthreads();
    }
}

// ---------------------------------------------------------------------------
// 2) fp16x3 HMMA GEMM, balanced grid of 296 CTAs (exactly 2 per SM).
//    i<8: 19 splits (26/27 chunks), i>=8: 18 splits (28/29 chunks).
//    Corrections (ah*wl, al*wh) use fp16 accumulators.
// ---------------------------------------------------------------------------
__global__ __launch_bounds__(256, 2) void k_gemm(const float* __restrict__ Wg) {
    extern __shared__ char smem[];
    const uint32_t sb = smem_u32(smem);

    // CTA -> (i, split j, chunk range)
    int i, j, nch, st;
    {
        const int c = blockIdx.x;
        if (c < 152) {           // 8 i's x 19 splits
            i = c / 19; j = c - i * 19;
            nch = 26 + (j < 18); st = j * 26 + min(j, 18);
        } else {                 // 8 i's x 18 splits
            const int d = c - 152;
            const int q = d / 18;
            i = 8 + q; j = d - q * 18;
            nch = 28 + (j < 8);  st = j * 28 + min(j, 8);
        }
    }
    const int r0 = st * KB;
    const int t = threadIdx.x;
    const int warp = t >> 5, lane = t & 31;
    const int wm = warp >> 2, wn = warp & 3;
    const float* Wi = Wg + (size_t)i * CO_ * NR_;
    const __half* Xh = g_xhi + (size_t)i * B_ * NR_;
    const __half* Xl = g_xlo + (size_t)i * B_ * NR_;

    float acc[2][5][4];
    uint32_t accC[2][5][2];      // fp16 correction accumulators
#pragma unroll
    for (int m = 0; m < 2; m++)
#pragma unroll
        for (int n = 0; n < 5; n++) {
#pragma unroll
            for (int q = 0; q < 4; q++) acc[m][n][q] = 0.f;
            accC[m][n][0] = 0u; accC[m][n][1] = 0u;
        }

    const int tA = lane >> 3;
    const int a_ml = (tA & 1) * 8 + (lane & 7);
    const int a_ko = (tA >> 1) * 8;
    const int b_bn = lane & 7;
    const int b_ko = (tA & 1) * 8;
    const int b_p  = tA >> 1;
    const int tC   = (lane >> 3) & 1;

    const int wrow = t >> 3, wk4 = t & 7;
    float4 wr[5];

#define LDGW(nn) { \
        const float* wp = Wi + (size_t)wrow * NR_ + r0 + (nn) * KB + wk4 * 4; \
        _Pragma("unroll") \
        for (int q = 0; q < 5; q++) wr[q] = *(const float4*)(wp + (size_t)q * 32 * NR_); }

#define XCP(nn, ss) { \
        const int xrow = t >> 2, xk8 = (t & 3) * 8; \
        const size_t so = (size_t)xrow * NR_ + r0 + (nn) * KB + xk8; \
        const uint32_t d = (uint32_t)((xrow * 40 + xk8) * 2) + (ss) * 5120; \
        cp16(sb + XSH_OFF + d, Xh + so); \
        cp16(sb + XSL_OFF + d, Xl + so); \
        cp_commit(); }

    XCP(0, 0);
    if (nch > 1) XCP(1, 1);
    LDGW(0);

    for (int n = 0; n < nch; n++) {
        const int s2 = n & 1, s3 = n % 3;
        __syncthreads();                 // closes compute(n-1)
#pragma unroll
        for (int q = 0; q < 5; q++) {
            union { __half h[4]; uint2 u; } ph, pl;
            hsplit(wr[q].x, ph.h[0], pl.h[0]);
            hsplit(wr[q].y, ph.h[1], pl.h[1]);
            hsplit(wr[q].z, ph.h[2], pl.h[2]);
            hsplit(wr[q].w, ph.h[3], pl.h[3]);
            const uint32_t d = (uint32_t)(((wrow + q * 32) * 40 + wk4 * 4) * 2)
                             + s2 * 12800;
            *(uint2*)(smem + WSH_OFF + d) = ph.u;
            *(uint2*)(smem + WSL_OFF + d) = pl.u;
        }
        if (n + 1 < nch) LDGW(n + 1);
        if (n + 2 < nch) { XCP(n + 2, (n + 2) % 3); }
        if (n + 2 < nch)      cp_wait<2>();
        else if (n + 1 < nch) cp_wait<1>();
        else                  cp_wait<0>();
        __syncthreads();                 // ws[s2] + xs[s3] ready

        const uint32_t wsh = sb + WSH_OFF + s2 * 12800;
        const uint32_t wsl = sb + WSL_OFF + s2 * 12800;
        const uint32_t xsh = sb + XSH_OFF + s3 * 5120;
        const uint32_t xsl = sb + XSL_OFF + s3 * 5120;
#pragma unroll
        for (int kb = 0; kb < 2; kb++) {
            uint32_t ah[2][4], al[2][4];
#pragma unroll
            for (int mt = 0; mt < 2; mt++) {
                const uint32_t ao =
                    (uint32_t)(((wm * 32 + mt * 16 + a_ml) * 40 + kb * 16 + a_ko) * 2);
                ldsm4(ah[mt], xsh + ao);
                ldsm4(al[mt], xsl + ao);
            }
            uint32_t bh[5][2], bl[5][2];
#pragma unroll
            for (int p = 0; p < 2; p++) {
                const uint32_t bo = (uint32_t)(
                    ((wn * 40 + (2 * p + b_p) * 8 + b_bn) * 40 + kb * 16 + b_ko) * 2);
                ldsm4(&bh[2 * p][0], wsh + bo);
                ldsm4(&bl[2 * p][0], wsl + bo);
            }
            {
                const uint32_t bo = (uint32_t)(
                    ((wn * 40 + 32 + b_bn) * 40 + kb * 16 + tC * 8) * 2);
                ldsm2(&bh[4][0], wsh + bo);
                ldsm2(&bl[4][0], wsl + bo);
            }
            // main term fp32-acc; corrections fp16-acc
#pragma unroll
            for (int mt = 0; mt < 2; mt++)
#pragma unroll
                for (int nf = 0; nf < 5; nf++) mma16816(acc[mt][nf], ah[mt], bh[nf]);
#pragma unroll
            for (int mt = 0; mt < 2; mt++)
#pragma unroll
                for (int nf = 0; nf < 5; nf++) mma16816h(accC[mt][nf], ah[mt], bl[nf]);
#pragma unroll
            for (int mt = 0; mt < 2; mt++)
#pragma unroll
                for (int nf = 0; nf < 5; nf++) mma16816h(accC[mt][nf], al[mt], bh[nf]);
        }
    }

    // fold fp16 correction accs into fp32 accs
#pragma unroll
    for (int mt = 0; mt < 2; mt++)
#pragma unroll
        for (int nf = 0; nf < 5; nf++) {
            const __half2 c0 = *(const __half2*)&accC[mt][nf][0];
            const __half2 c1 = *(const __half2*)&accC[mt][nf][1];
            acc[mt][nf][0] += __low2float(c0);
            acc[mt][nf][1] += __high2float(c0);
            acc[mt][nf][2] += __low2float(c1);
            acc[mt][nf][3] += __high2float(c1);
        }

    // epilogue: g_part[j][b][i][co]
    float* base = g_part + (size_t)j * (B_ * IC_ * CO_) + (size_t)i * CO_;
#pragma unroll
    for (int mt = 0; mt < 2; mt++) {
        const int b = wm * 32 + mt * 16 + (lane >> 2);
#pragma unroll
        for (int nf = 0; nf < 5; nf++) {
            const int co = wn * 40 + nf * 8 + (lane & 3) * 2;
            float* d0 = base + (size_t)b * (IC_ * CO_) + co;
            *(float2*)d0 = make_float2(acc[mt][nf][0], acc[mt][nf][1]);
            *(float2*)(d0 + 8 * IC_ * CO_) =
                make_float2(acc[mt][nf][2], acc[mt][nf][3]);   // b+8
        }
    }
}

// ---------------------------------------------------------------------------
// 3) Fused split-K reduce + routing + v + fc partials + (last CTA) final pred.
// ---------------------------------------------------------------------------
#define ISTR 1032
__global__ __launch_bounds__(1024) void k_route_all(const float* __restrict__ fcw,
                                                    const float* __restrict__ fcb,
                                                    float* __restrict__ out) {
    extern __shared__ float sm[];
    float* u_s  = sm;                       // [16][ISTR]
    float* v_s  = sm + 16 * ISTR;           // [1024]
    float* csh  = v_s + 1024;               // [16]
    float* bijs = csh + 16;                 // [16]
    float* ared = bijs + 16;                // [32]
    __shared__ int last;
    const int c = blockIdx.x, t = threadIdx.x;

    {   // split-K reduce; i<8 has 19 splits, i>=8 has 18
        const int o4 = t & 3, i = (t >> 2) & 15, b0 = t >> 6;
        const int ns = (i < 8) ? 19 : 18;
#pragma unroll
        for (int jj = 0; jj < 4; jj++) {
            const int b = b0 + 16 * jj;
            const size_t off = ((size_t)b * IC_ + i) * CO_ + c * OC_ + o4 * 4;
            float4 s = make_float4(0.f, 0.f, 0.f, 0.f);
#pragma unroll 19
            for (int sp = 0; sp < ns; sp++) {
                float4 p = *(const float4*)(g_part + (size_t)sp * (B_ * IC_ * CO_) + off);
                s.x += p.x; s.y += p.y; s.z += p.z; s.w += p.w;
            }
            *(float4*)(u_s + i * ISTR + b * 16 + o4 * 4) = s;
        }
    }
    if (t < 16) bijs[t] = 0.f;
    __syncthreads();

    for (int it = 0; it < 3; it++) {
        if (t < 32) {   // softmax over i, width-16 shuffles
            float bv = (t < 16) ? bijs[t] : -1e30f;
            float m = bv;
#pragma unroll
            for (int off = 8; off; off >>= 1)
                m = fmaxf(m, __shfl_xor_sync(0xffffffffu, m, off, 16));
            float e = expf(bv - m), sum = e;
#pragma unroll
            for (int off = 8; off; off >>= 1)
                sum += __shfl_xor_sync(0xffffffffu, sum, off, 16);
            if (t < 16) csh[t] = e / sum;
        }
        __syncthreads();
        {
            float s = 0.f;
#pragma unroll
            for (int i = 0; i < IC_; i++) s += csh[i] * u_s[i * ISTR + t];
            v_s[t] = s * fabsf(s) / (1.f + s * s);
        }
        __syncthreads();
        if (it < 2) {   // agreement
            const int w = t >> 5, l = t & 31;
            const int i = w & 15, j0 = (w >> 4) * 512;
            float a = 0.f;
            for (int jj = j0 + l; jj < j0 + 512; jj += 32)
                a += u_s[i * ISTR + jj] * v_s[jj];
#pragma unroll
            for (int off = 16; off; off >>= 1)
                a += __shfl_down_sync(0xffffffffu, a, off);
            if (l == 0) ared[(w >> 4) * 16 + i] = a;
            __syncthreads();
            if (t < 16) bijs[t] += (ared[t] + ared[16 + t]) * (1.0f / B_);
            __syncthreads();
        }
    }
    {
        const int b = t >> 4, o = t & 15;
        const float v = v_s[t];
        out[B_ + b * CO_ + c * OC_ + o] = v;
        float p = v * fcw[c * OC_ + o];
#pragma unroll
        for (int off = 8; off; off >>= 1)
            p += __shfl_down_sync(0xffffffffu, p, off, 16);
        if (o == 0) g_fcp[c * B_ + b] = p;
    }
    __threadfence();
    if (t == 0) last = (atomicAdd(&g_ctr, 1) == NC_ - 1);
    __syncthreads();
    if (last) {
        if (t < B_) {
            float s = fcb[0];
#pragma unroll
            for (int cc = 0; cc < NC_; cc++) s += g_fcp[cc * B_ + t];
            out[t] = 1.f / (1.f + expf(-s));
        }
        if (t == 0) g_ctr = 0;   // reset for graph replay
    }
}

// ---------------------------------------------------------------------------
extern "C" void kernel_launch(void* const* d_in, const int* in_sizes, int n_in,
                              void* d_out, int out_size) {
    const float* x   = (const float*)d_in[0];
    const float* W   = (const float*)d_in[1];
    const float* fcw = (const float*)d_in[2];
    const float* fcb = (const float*)d_in[3];
    float* out = (float*)d_out;

    const int route_smem = (16 * ISTR + 1024 + 16 + 16 + 32) * 4;
    cudaFuncSetAttribute(k_gemm, cudaFuncAttributeMaxDynamicSharedMemorySize, SMEM_G);
    cudaFuncSetAttribute(k_route_all, cudaFuncAttributeMaxDynamicSharedMemorySize,
                         route_smem);

    k_transpose<<<dim3(NR_ / 256, B_), 256>>>(x);
    k_gemm<<<296, 256, SMEM_G>>>(W);
    k_route_all<<<NC_, 1024, route_smem>>>(fcw, fcb, out);
}